// round 2
// baseline (speedup 1.0000x reference)
#include <cuda_runtime.h>
#include <math.h>

// ---------------------------------------------------------------------------
// Problem constants (fixed shapes from the reference)
// ---------------------------------------------------------------------------
constexpr int Vv  = 32000;
constexpr int Dd  = 1024;
constexpr int Hh  = 16;
constexpr int Ll  = 4;
constexpr int Bb  = 4;
constexpr int Ss  = 1024;
constexpr int HDd = 64;           // Dd / Hh
constexpr int Mrows = Bb * Ss;    // 4096 token rows
constexpr int Dff = 4 * Dd;       // 4096
constexpr float EPSc = 1e-5f;

// ---------------------------------------------------------------------------
// Scratch: one big __device__ array (no allocations allowed anywhere)
// ---------------------------------------------------------------------------
constexpr size_t SZ_TOK = (size_t)Mrows * Dd;       // 4,194,304
constexpr size_t SZ_FF  = (size_t)Mrows * Dff;      // 16,777,216

constexpr size_t OFF_X = 0;
constexpr size_t OFF_H = OFF_X + SZ_TOK;
constexpr size_t OFF_Q = OFF_H + SZ_TOK;
constexpr size_t OFF_K = OFF_Q + SZ_TOK;
constexpr size_t OFF_V = OFF_K + SZ_TOK;
constexpr size_t OFF_A = OFF_V + SZ_TOK;
constexpr size_t OFF_F = OFF_A + SZ_TOK;
constexpr size_t SCRATCH_TOTAL = OFF_F + SZ_FF;     // 41,943,040 floats (~168 MB)

__device__ float g_scratch[SCRATCH_TOTAL];

// ---------------------------------------------------------------------------
// Embedding: x[b,s,:] = tok_emb[ids[b,s],:] + sinusoidal_pe(s,:)
// ---------------------------------------------------------------------------
__global__ void embed_kernel(const int* __restrict__ ids,
                             const float* __restrict__ tok,
                             float* __restrict__ x)
{
    const int row = blockIdx.x;           // 0..Mrows-1
    const int s   = row & (Ss - 1);
    const int id  = ids[row];
    const float* e = tok + (size_t)id * Dd;
    float* xr = x + (size_t)row * Dd;
    const float c = -logf(10000.0f) / (float)Dd;
    for (int d = threadIdx.x; d < Dd; d += blockDim.x) {
        int i2 = d & ~1;                  // arange(0, D, 2) value for this pair
        float fr  = expf((float)i2 * c);
        float arg = (float)s * fr;
        float pe  = (d & 1) ? cosf(arg) : sinf(arg);
        xr[d] = e[d] + pe;
    }
}

// ---------------------------------------------------------------------------
// LayerNorm: one block (256 threads) per row of 1024
// ---------------------------------------------------------------------------
__global__ __launch_bounds__(256)
void ln_kernel(const float* __restrict__ x,
               const float* __restrict__ g,
               const float* __restrict__ b,
               float* __restrict__ out)
{
    __shared__ float sa[8], sb[8];
    const int row = blockIdx.x;
    const float* xr = x + (size_t)row * Dd;

    float v[4];
    float s0 = 0.f, s1 = 0.f;
#pragma unroll
    for (int i = 0; i < 4; i++) {
        v[i] = xr[threadIdx.x + i * 256];
        s0 += v[i];
        s1 += v[i] * v[i];
    }
#pragma unroll
    for (int o = 16; o; o >>= 1) {
        s0 += __shfl_xor_sync(0xffffffffu, s0, o);
        s1 += __shfl_xor_sync(0xffffffffu, s1, o);
    }
    const int lane = threadIdx.x & 31, w = threadIdx.x >> 5;
    if (lane == 0) { sa[w] = s0; sb[w] = s1; }
    __syncthreads();
    if (threadIdx.x < 32) {
        s0 = (lane < 8) ? sa[lane] : 0.f;
        s1 = (lane < 8) ? sb[lane] : 0.f;
#pragma unroll
        for (int o = 4; o; o >>= 1) {
            s0 += __shfl_xor_sync(0xffffffffu, s0, o);
            s1 += __shfl_xor_sync(0xffffffffu, s1, o);
        }
        if (lane == 0) { sa[0] = s0; sb[0] = s1; }
    }
    __syncthreads();
    const float mean = sa[0] * (1.0f / (float)Dd);
    const float var  = sb[0] * (1.0f / (float)Dd) - mean * mean;
    const float rstd = rsqrtf(var + EPSc);

    float* orow = out + (size_t)row * Dd;
#pragma unroll
    for (int i = 0; i < 4; i++) {
        const int d = threadIdx.x + i * 256;
        orow[d] = (v[i] - mean) * rstd * g[d] + b[d];
    }
}

// ---------------------------------------------------------------------------
// SGEMM: C[M,N] = A[M,K] @ W[K,N] + bias[N]  (+ residual / gelu epilogue)
// Tiles 128x128x16, 256 threads, 8x8 per thread, double-buffered SMEM with
// register-staged prefetch (one __syncthreads per K-step).
// M,N,K all multiples of the tile sizes.
// ---------------------------------------------------------------------------
__device__ __forceinline__ float gelu_f(float x)
{
    return 0.5f * x * (1.0f + erff(x * 0.70710678118654752f));
}

enum { EPI_NONE = 0, EPI_RES = 1, EPI_GELU = 2 };

template <int EPI>
__global__ __launch_bounds__(256)
void gemm_kernel(const float* __restrict__ A,
                 const float* __restrict__ W,
                 const float* __restrict__ bias,
                 const float* __restrict__ R,
                 float* __restrict__ C,
                 int N, int K)
{
    __shared__ float As[2][16][132];   // [buf][k][m], padded
    __shared__ float Bs[2][16][128];   // [buf][k][n]

    const int tid = threadIdx.x;
    const int tx  = tid & 15;       // col group: 8 cols
    const int ty  = tid >> 4;       // row group: 8 rows
    const int m0  = blockIdx.y * 128;
    const int n0  = blockIdx.x * 128;

    // Per-thread load coordinates (2 float4 each for A and B tiles)
    const int arow0 = tid >> 1;                 // 0..127  (A rows, j=0)
    const int acol0 = (tid & 1) << 3;           // 0 or 8  -> covers k 0..7 / 8..15
    const int brow0 = tid >> 5;                 // 0..7    (B rows, j=0)
    const int bcol0 = (tid & 31) << 2;          // 0..124

    float acc[8][8];
#pragma unroll
    for (int i = 0; i < 8; i++)
#pragma unroll
        for (int j = 0; j < 8; j++) acc[i][j] = 0.f;

    // ---- preload tile 0 into buffer 0 ----
    {
        const float4 a0 = *reinterpret_cast<const float4*>(
            A + (size_t)(m0 + arow0) * K + acol0);
        const float4 a1 = *reinterpret_cast<const float4*>(
            A + (size_t)(m0 + arow0) * K + acol0 + 4);
        As[0][acol0 + 0][arow0] = a0.x;
        As[0][acol0 + 1][arow0] = a0.y;
        As[0][acol0 + 2][arow0] = a0.z;
        As[0][acol0 + 3][arow0] = a0.w;
        As[0][acol0 + 4][arow0] = a1.x;
        As[0][acol0 + 5][arow0] = a1.y;
        As[0][acol0 + 6][arow0] = a1.z;
        As[0][acol0 + 7][arow0] = a1.w;
        *reinterpret_cast<float4*>(&Bs[0][brow0][bcol0]) =
            *reinterpret_cast<const float4*>(W + (size_t)brow0 * N + n0 + bcol0);
        *reinterpret_cast<float4*>(&Bs[0][brow0 + 8][bcol0]) =
            *reinterpret_cast<const float4*>(W + (size_t)(brow0 + 8) * N + n0 + bcol0);
    }
    __syncthreads();

    int buf = 0;
    for (int k0 = 0; k0 < K; k0 += 16) {
        const bool has_next = (k0 + 16) < K;
        float4 pa0, pa1, pb0, pb1;
        if (has_next) {
            const int kn = k0 + 16;
            pa0 = *reinterpret_cast<const float4*>(
                A + (size_t)(m0 + arow0) * K + kn + acol0);
            pa1 = *reinterpret_cast<const float4*>(
                A + (size_t)(m0 + arow0) * K + kn + acol0 + 4);
            pb0 = *reinterpret_cast<const float4*>(
                W + (size_t)(kn + brow0) * N + n0 + bcol0);
            pb1 = *reinterpret_cast<const float4*>(
                W + (size_t)(kn + brow0 + 8) * N + n0 + bcol0);
        }

#pragma unroll
        for (int kk = 0; kk < 16; kk++) {
            float a[8], b[8];
            float4 a0 = *reinterpret_cast<const float4*>(&As[buf][kk][ty * 8]);
            float4 a1 = *reinterpret_cast<const float4*>(&As[buf][kk][ty * 8 + 4]);
            float4 b0 = *reinterpret_cast<const float4*>(&Bs[buf][kk][tx * 8]);
            float4 b1 = *reinterpret_cast<const float4*>(&Bs[buf][kk][tx * 8 + 4]);
            a[0] = a0.x; a[1] = a0.y; a[2] = a0.z; a[3] = a0.w;
            a[4] = a1.x; a[5] = a1.y; a[6] = a1.z; a[7] = a1.w;
            b[0] = b0.x; b[1] = b0.y; b[2] = b0.z; b[3] = b0.w;
            b[4] = b1.x; b[5] = b1.y; b[6] = b1.z; b[7] = b1.w;
#pragma unroll
            for (int i = 0; i < 8; i++)
#pragma unroll
                for (int j = 0; j < 8; j++)
                    acc[i][j] += a[i] * b[j];
        }

        if (has_next) {
            const int nb = buf ^ 1;
            As[nb][acol0 + 0][arow0] = pa0.x;
            As[nb][acol0 + 1][arow0] = pa0.y;
            As[nb][acol0 + 2][arow0] = pa0.z;
            As[nb][acol0 + 3][arow0] = pa0.w;
            As[nb][acol0 + 4][arow0] = pa1.x;
            As[nb][acol0 + 5][arow0] = pa1.y;
            As[nb][acol0 + 6][arow0] = pa1.z;
            As[nb][acol0 + 7][arow0] = pa1.w;
            *reinterpret_cast<float4*>(&Bs[nb][brow0][bcol0])     = pb0;
            *reinterpret_cast<float4*>(&Bs[nb][brow0 + 8][bcol0]) = pb1;
            __syncthreads();
            buf = nb;
        }
    }

    // Epilogue
#pragma unroll
    for (int i = 0; i < 8; i++) {
        const int row = m0 + ty * 8 + i;
#pragma unroll
        for (int j4 = 0; j4 < 2; j4++) {
            const int col = n0 + tx * 8 + j4 * 4;
            float4 bv = *reinterpret_cast<const float4*>(bias + col);
            float4 o;
            o.x = acc[i][j4 * 4 + 0] + bv.x;
            o.y = acc[i][j4 * 4 + 1] + bv.y;
            o.z = acc[i][j4 * 4 + 2] + bv.z;
            o.w = acc[i][j4 * 4 + 3] + bv.w;
            if (EPI == EPI_RES) {
                float4 r = *reinterpret_cast<const float4*>(
                    R + (size_t)row * N + col);
                o.x += r.x; o.y += r.y; o.z += r.z; o.w += r.w;
            } else if (EPI == EPI_GELU) {
                o.x = gelu_f(o.x); o.y = gelu_f(o.y);
                o.z = gelu_f(o.z); o.w = gelu_f(o.w);
            }
            *reinterpret_cast<float4*>(C + (size_t)row * N + col) = o;
        }
    }
}

// ---------------------------------------------------------------------------
// Causal attention, one thread per query, online softmax, K/V tiles in SMEM.
// q/k/v layout: [B*S, D] with head h occupying columns [h*64, h*64+64).
// ---------------------------------------------------------------------------
__global__ __launch_bounds__(64)
void attn_kernel(const float* __restrict__ q,
                 const float* __restrict__ k,
                 const float* __restrict__ v,
                 const int* __restrict__ amask,
                 float* __restrict__ o)
{
    __shared__ float Ks[64][64];
    __shared__ float Vs[64][64];
    __shared__ int   msk[64];

    const int t  = threadIdx.x;
    const int bh = blockIdx.y;
    const int b  = bh >> 4;           // / Hh
    const int h  = bh & 15;
    const int qt = blockIdx.x;        // query tile
    const int qi = qt * 64 + t;       // this thread's query position

    const size_t qoff = ((size_t)(b * Ss + qi)) * Dd + h * HDd;

    float4 q4[16];
#pragma unroll
    for (int i = 0; i < 16; i++)
        q4[i] = *reinterpret_cast<const float4*>(q + qoff + i * 4);

    float4 oa[16];
#pragma unroll
    for (int i = 0; i < 16; i++) oa[i] = make_float4(0.f, 0.f, 0.f, 0.f);

    float mrun = -1e30f, lrun = 0.f;
    const float scale = 0.125f;       // 1/sqrt(64)

    for (int kt = 0; kt <= qt; kt++) {
        __syncthreads();              // previous tile fully consumed
#pragma unroll
        for (int i = 0; i < 16; i++) {
            const int f = i * 64 + t;
            const int r = f >> 4;
            const int c = (f & 15) << 2;
            const size_t src =
                ((size_t)(b * Ss + kt * 64 + r)) * Dd + h * HDd + c;
            *reinterpret_cast<float4*>(&Ks[r][c]) =
                *reinterpret_cast<const float4*>(k + src);
            *reinterpret_cast<float4*>(&Vs[r][c]) =
                *reinterpret_cast<const float4*>(v + src);
        }
        msk[t] = amask[b * Ss + kt * 64 + t];
        __syncthreads();

        const int kmax = (kt == qt) ? (t + 1) : 64;   // causal bound
        for (int kk = 0; kk < kmax; kk++) {
            if (!msk[kk]) continue;                   // block-uniform
            const float4* kr = reinterpret_cast<const float4*>(&Ks[kk][0]);
            float sA = 0.f, sB = 0.f, sC = 0.f, sD = 0.f;
#pragma unroll
            for (int i = 0; i < 16; i++) {
                float4 kv = kr[i];
                sA += q4[i].x * kv.x;
                sB += q4[i].y * kv.y;
                sC += q4[i].z * kv.z;
                sD += q4[i].w * kv.w;
            }
            const float sc = (sA + sB + sC + sD) * scale;
            const float mn = fmaxf(mrun, sc);
            const float alpha = __expf(mrun - mn);
            const float p     = __expf(sc - mn);
            lrun = lrun * alpha + p;
            mrun = mn;
            const float4* vr = reinterpret_cast<const float4*>(&Vs[kk][0]);
#pragma unroll
            for (int i = 0; i < 16; i++) {
                float4 vv = vr[i];
                oa[i].x = oa[i].x * alpha + p * vv.x;
                oa[i].y = oa[i].y * alpha + p * vv.y;
                oa[i].z = oa[i].z * alpha + p * vv.z;
                oa[i].w = oa[i].w * alpha + p * vv.w;
            }
        }
    }

    const float inv = (lrun > 0.f) ? (1.0f / lrun) : 0.f;
#pragma unroll
    for (int i = 0; i < 16; i++) {
        float4 ov = make_float4(oa[i].x * inv, oa[i].y * inv,
                                oa[i].z * inv, oa[i].w * inv);
        *reinterpret_cast<float4*>(o + qoff + i * 4) = ov;
    }
}

// ---------------------------------------------------------------------------
// Launch: embed -> 4x [ln1, QKV, attn, O+res, ln2, FF1(gelu), FF2+res] -> lnf
// All on default stream; graph-capturable (no sync, no alloc, no memcpy).
// ---------------------------------------------------------------------------
extern "C" void kernel_launch(void* const* d_in, const int* in_sizes, int n_in,
                              void* d_out, int out_size)
{
    const int*   ids   = (const int*)d_in[0];
    const int*   amask = (const int*)d_in[1];
    const float* tok   = (const float*)d_in[2];
    const float* ln1g  = (const float*)d_in[3];
    const float* ln1b  = (const float*)d_in[4];
    const float* wq    = (const float*)d_in[5];
    const float* bq    = (const float*)d_in[6];
    const float* wk    = (const float*)d_in[7];
    const float* bk    = (const float*)d_in[8];
    const float* wv    = (const float*)d_in[9];
    const float* bv    = (const float*)d_in[10];
    const float* wo    = (const float*)d_in[11];
    const float* bo    = (const float*)d_in[12];
    const float* ln2g  = (const float*)d_in[13];
    const float* ln2b  = (const float*)d_in[14];
    const float* w1    = (const float*)d_in[15];
    const float* b1    = (const float*)d_in[16];
    const float* w2    = (const float*)d_in[17];
    const float* b2    = (const float*)d_in[18];
    const float* lnfg  = (const float*)d_in[19];
    const float* lnfb  = (const float*)d_in[20];
    float* out = (float*)d_out;

    float* scratch = nullptr;
    cudaGetSymbolAddress((void**)&scratch, g_scratch);

    float* X  = scratch + OFF_X;
    float* Hb = scratch + OFF_H;
    float* Qb = scratch + OFF_Q;
    float* Kb = scratch + OFF_K;
    float* Vb = scratch + OFF_V;
    float* Ab = scratch + OFF_A;
    float* Fb = scratch + OFF_F;

    const dim3 gD(Dd / 128, Mrows / 128);    // (8, 32)  for N=1024
    const dim3 gF(Dff / 128, Mrows / 128);   // (32, 32) for N=4096
    const dim3 gAttn(Ss / 64, Bb * Hh);      // (16, 64)

    embed_kernel<<<Mrows, 256>>>(ids, tok, X);

    for (int l = 0; l < Ll; l++) {
        const size_t wOff = (size_t)l * Dd * Dd;
        const size_t fOff = (size_t)l * Dd * Dff;

        ln_kernel<<<Mrows, 256>>>(X, ln1g + l * Dd, ln1b + l * Dd, Hb);

        gemm_kernel<EPI_NONE><<<gD, 256>>>(Hb, wq + wOff, bq + l * Dd,
                                           nullptr, Qb, Dd, Dd);
        gemm_kernel<EPI_NONE><<<gD, 256>>>(Hb, wk + wOff, bk + l * Dd,
                                           nullptr, Kb, Dd, Dd);
        gemm_kernel<EPI_NONE><<<gD, 256>>>(Hb, wv + wOff, bv + l * Dd,
                                           nullptr, Vb, Dd, Dd);

        attn_kernel<<<gAttn, 64>>>(Qb, Kb, Vb, amask, Ab);

        gemm_kernel<EPI_RES><<<gD, 256>>>(Ab, wo + wOff, bo + l * Dd,
                                          X, X, Dd, Dd);

        ln_kernel<<<Mrows, 256>>>(X, ln2g + l * Dd, ln2b + l * Dd, Hb);

        gemm_kernel<EPI_GELU><<<gF, 256>>>(Hb, w1 + fOff, b1 + l * Dff,
                                           nullptr, Fb, Dff, Dd);
        gemm_kernel<EPI_RES><<<gD, 256>>>(Fb, w2 + fOff, b2 + l * Dd,
                                          X, X, Dd, Dff);
    }

    ln_kernel<<<Mrows, 256>>>(X, lnfg, lnfb, out);
}

// round 10
// speedup vs baseline: 1.7568x; 1.7568x over previous
#include <cuda_runtime.h>
#include <cuda_bf16.h>
#include <math.h>
#include <stdint.h>

// ---------------------------------------------------------------------------
// Problem constants
// ---------------------------------------------------------------------------
constexpr int Dd  = 1024;
constexpr int Hh  = 16;
constexpr int Ll  = 4;
constexpr int Bb  = 4;
constexpr int Ss  = 1024;
constexpr int HDd = 64;
constexpr int Mrows = Bb * Ss;    // 4096
constexpr int Dff = 4 * Dd;       // 4096
constexpr float EPSc = 1e-5f;

// ---------------------------------------------------------------------------
// Scratch
// ---------------------------------------------------------------------------
constexpr size_t SZ_TOK = (size_t)Mrows * Dd;
constexpr size_t SZ_FF  = (size_t)Mrows * Dff;
constexpr size_t OFF_X = 0;
constexpr size_t OFF_H = OFF_X + SZ_TOK;
constexpr size_t OFF_Q = OFF_H + SZ_TOK;
constexpr size_t OFF_K = OFF_Q + SZ_TOK;
constexpr size_t OFF_V = OFF_K + SZ_TOK;
constexpr size_t OFF_A = OFF_V + SZ_TOK;
constexpr size_t OFF_F = OFF_A + SZ_TOK;
constexpr size_t SCRATCH_TOTAL = OFF_F + SZ_FF;
__device__ float g_scratch[SCRATCH_TOTAL];

// ---------------------------------------------------------------------------
// Embedding
// ---------------------------------------------------------------------------
__global__ void embed_kernel(const int* __restrict__ ids,
                             const float* __restrict__ tok,
                             float* __restrict__ x)
{
    const int row = blockIdx.x;
    const int s   = row & (Ss - 1);
    const int id  = ids[row];
    const float* e = tok + (size_t)id * Dd;
    float* xr = x + (size_t)row * Dd;
    const float c = -logf(10000.0f) / (float)Dd;
    for (int d = threadIdx.x; d < Dd; d += blockDim.x) {
        int i2 = d & ~1;
        float fr  = expf((float)i2 * c);
        float arg = (float)s * fr;
        float pe  = (d & 1) ? cosf(arg) : sinf(arg);
        xr[d] = e[d] + pe;
    }
}

// ---------------------------------------------------------------------------
// LayerNorm
// ---------------------------------------------------------------------------
__global__ __launch_bounds__(256)
void ln_kernel(const float* __restrict__ x,
               const float* __restrict__ g,
               const float* __restrict__ b,
               float* __restrict__ out)
{
    __shared__ float sa[8], sb[8];
    const int row = blockIdx.x;
    const float* xr = x + (size_t)row * Dd;

    float v[4];
    float s0 = 0.f, s1 = 0.f;
#pragma unroll
    for (int i = 0; i < 4; i++) {
        v[i] = xr[threadIdx.x + i * 256];
        s0 += v[i];
        s1 += v[i] * v[i];
    }
#pragma unroll
    for (int o = 16; o; o >>= 1) {
        s0 += __shfl_xor_sync(0xffffffffu, s0, o);
        s1 += __shfl_xor_sync(0xffffffffu, s1, o);
    }
    const int lane = threadIdx.x & 31, w = threadIdx.x >> 5;
    if (lane == 0) { sa[w] = s0; sb[w] = s1; }
    __syncthreads();
    if (threadIdx.x < 32) {
        s0 = (lane < 8) ? sa[lane] : 0.f;
        s1 = (lane < 8) ? sb[lane] : 0.f;
#pragma unroll
        for (int o = 4; o; o >>= 1) {
            s0 += __shfl_xor_sync(0xffffffffu, s0, o);
            s1 += __shfl_xor_sync(0xffffffffu, s1, o);
        }
        if (lane == 0) { sa[0] = s0; sb[0] = s1; }
    }
    __syncthreads();
    const float mean = sa[0] * (1.0f / (float)Dd);
    const float var  = sb[0] * (1.0f / (float)Dd) - mean * mean;
    const float rstd = rsqrtf(var + EPSc);

    float* orow = out + (size_t)row * Dd;
#pragma unroll
    for (int i = 0; i < 4; i++) {
        const int d = threadIdx.x + i * 256;
        orow[d] = (v[i] - mean) * rstd * g[d] + b[d];
    }
}

// ---------------------------------------------------------------------------
// mma.sync helpers (baseline sm_80+ PTX; legal on sm_103 target)
// ---------------------------------------------------------------------------
__device__ __forceinline__ void ldsm_x4(uint32_t addr, uint32_t r[4]) {
    asm volatile("ldmatrix.sync.aligned.m8n8.x4.shared.b16 {%0,%1,%2,%3}, [%4];"
                 : "=r"(r[0]), "=r"(r[1]), "=r"(r[2]), "=r"(r[3]) : "r"(addr));
}
__device__ __forceinline__ void ldsm_x2(uint32_t addr, uint32_t r[2]) {
    asm volatile("ldmatrix.sync.aligned.m8n8.x2.shared.b16 {%0,%1}, [%2];"
                 : "=r"(r[0]), "=r"(r[1]) : "r"(addr));
}
__device__ __forceinline__ void mma_bf16(float c[4], const uint32_t a[4],
                                         const uint32_t b[2]) {
    asm volatile(
        "mma.sync.aligned.m16n8k16.row.col.f32.bf16.bf16.f32 "
        "{%0,%1,%2,%3}, {%4,%5,%6,%7}, {%8,%9}, {%0,%1,%2,%3};"
        : "+f"(c[0]), "+f"(c[1]), "+f"(c[2]), "+f"(c[3])
        : "r"(a[0]), "r"(a[1]), "r"(a[2]), "r"(a[3]), "r"(b[0]), "r"(b[1]));
}

__device__ __forceinline__ uint32_t pk_bf2(__nv_bfloat16 a, __nv_bfloat16 b) {
    __nv_bfloat162 t; t.x = a; t.y = b;
    return *reinterpret_cast<uint32_t*>(&t);
}

// convert 16 floats -> 16 hi-bf16 + 16 lo-bf16, stored as 2x uint4 each
__device__ __forceinline__ void cvt_store16(char* dsthi, char* dstlo,
                                            const float* f) {
    uint32_t hw[8], lw[8];
#pragma unroll
    for (int i = 0; i < 8; i++) {
        float x0 = f[2 * i], x1 = f[2 * i + 1];
        __nv_bfloat16 h0 = __float2bfloat16(x0);
        __nv_bfloat16 h1 = __float2bfloat16(x1);
        __nv_bfloat16 l0 = __float2bfloat16(x0 - __bfloat162float(h0));
        __nv_bfloat16 l1 = __float2bfloat16(x1 - __bfloat162float(h1));
        hw[i] = pk_bf2(h0, h1);
        lw[i] = pk_bf2(l0, l1);
    }
    reinterpret_cast<uint4*>(dsthi)[0] = make_uint4(hw[0], hw[1], hw[2], hw[3]);
    reinterpret_cast<uint4*>(dsthi)[1] = make_uint4(hw[4], hw[5], hw[6], hw[7]);
    reinterpret_cast<uint4*>(dstlo)[0] = make_uint4(lw[0], lw[1], lw[2], lw[3]);
    reinterpret_cast<uint4*>(dstlo)[1] = make_uint4(lw[4], lw[5], lw[6], lw[7]);
}

// ---------------------------------------------------------------------------
// HMMA GEMM: C[M,N] = A[M,K] @ W[K,N] + bias (+ residual / gelu)
// 128x128 CTA tile, K-slab 32, bf16 hi/lo 3-pass, double-buffered SMEM.
// ---------------------------------------------------------------------------
__device__ __forceinline__ float gelu_f(float x)
{
    return 0.5f * x * (1.0f + erff(x * 0.70710678118654752f));
}

enum { EPI_NONE = 0, EPI_RES = 1, EPI_GELU = 2 };

constexpr uint32_t ROWB  = 80;            // bytes per smem row (32 bf16 + pad)
constexpr uint32_t ARR   = 128 * ROWB;    // 10240 B, one 128x32 bf16 tile
constexpr uint32_t BUFB  = 4 * ARR;       // Ah, Al, Bh, Bl
constexpr uint32_t GSMEM = 2 * BUFB;      // 81920 B double-buffered

template <int EPI>
__global__ __launch_bounds__(256)
void mma_gemm(const float* __restrict__ A,
              const float* __restrict__ W,
              const float* __restrict__ bias,
              const float* __restrict__ R,
              float* __restrict__ C,
              int N, int K)
{
    extern __shared__ char sm[];
    const uint32_t sb = (uint32_t)__cvta_generic_to_shared(sm);

    const int tid  = threadIdx.x;
    const int wid  = tid >> 5, lane = tid & 31;
    const int wy   = wid >> 2, wx = wid & 3;
    const int m0   = blockIdx.y * 128;
    const int n0   = blockIdx.x * 128;

    // global loader coords
    const int am = tid >> 1;             // A row 0..127
    const int ak = (tid & 1) * 16;       // A k-offset 0/16
    const int bn = tid & 127;            // B n (W column)
    const int bk = (tid >> 7) * 16;      // B k-offset 0/16

    // ldmatrix per-lane base offsets (bytes within one buffer)
    const uint32_t a_off0 = (uint32_t)(wy * 64 + (lane & 15)) * ROWB
                          + ((uint32_t)(lane >> 4) << 4);
    const uint32_t b_off0 = (uint32_t)(wx * 32 + (lane & 7)) * ROWB
                          + (((uint32_t)(lane >> 3) & 1u) << 4);

    float acc[4][4][4];
#pragma unroll
    for (int i = 0; i < 4; i++)
#pragma unroll
        for (int j = 0; j < 4; j++)
#pragma unroll
            for (int q = 0; q < 4; q++) acc[i][j][q] = 0.f;

    const int nslabs = K >> 5;

    // ---- preload slab 0 into buffer 0 ----
    {
        float fa[16];
        const float* ap = A + (size_t)(m0 + am) * K + ak;
#pragma unroll
        for (int i = 0; i < 4; i++) {
            float4 v = reinterpret_cast<const float4*>(ap)[i];
            fa[4 * i] = v.x; fa[4 * i + 1] = v.y;
            fa[4 * i + 2] = v.z; fa[4 * i + 3] = v.w;
        }
        cvt_store16(sm + (size_t)am * ROWB + ak * 2,
                    sm + ARR + (size_t)am * ROWB + ak * 2, fa);
        float fb[16];
        const float* wp = W + (size_t)bk * N + n0 + bn;
#pragma unroll
        for (int i = 0; i < 16; i++) fb[i] = wp[(size_t)i * N];
        cvt_store16(sm + 2 * ARR + (size_t)bn * ROWB + bk * 2,
                    sm + 3 * ARR + (size_t)bn * ROWB + bk * 2, fb);
    }
    __syncthreads();

    for (int s = 0; s < nslabs; s++) {
        const int buf = s & 1;
        const uint32_t base = (uint32_t)buf * BUFB;

        // prefetch next slab into registers
        float fa[16], fb[16];
        const bool has_next = (s + 1) < nslabs;
        if (has_next) {
            const int k0 = (s + 1) * 32;
            const float* ap = A + (size_t)(m0 + am) * K + k0 + ak;
#pragma unroll
            for (int i = 0; i < 4; i++) {
                float4 v = reinterpret_cast<const float4*>(ap)[i];
                fa[4 * i] = v.x; fa[4 * i + 1] = v.y;
                fa[4 * i + 2] = v.z; fa[4 * i + 3] = v.w;
            }
            const float* wp = W + (size_t)(k0 + bk) * N + n0 + bn;
#pragma unroll
            for (int i = 0; i < 16; i++) fb[i] = wp[(size_t)i * N];
        }

        // compute from current buffer: two k16 steps
#pragma unroll
        for (int ks = 0; ks < 2; ks++) {
            uint32_t ah[4][4], al[4][4], bh[4][2], bl[4][2];
#pragma unroll
            for (int mi = 0; mi < 4; mi++) {
                const uint32_t ao = sb + base + a_off0
                                  + (uint32_t)mi * 16 * ROWB + ks * 32;
                ldsm_x4(ao, ah[mi]);
                ldsm_x4(ao + ARR, al[mi]);
            }
#pragma unroll
            for (int ni = 0; ni < 4; ni++) {
                const uint32_t bo = sb + base + 2 * ARR + b_off0
                                  + (uint32_t)ni * 8 * ROWB + ks * 32;
                ldsm_x2(bo, bh[ni]);
                ldsm_x2(bo + ARR, bl[ni]);
            }
#pragma unroll
            for (int mi = 0; mi < 4; mi++)
#pragma unroll
                for (int ni = 0; ni < 4; ni++) {
                    mma_bf16(acc[mi][ni], ah[mi], bh[ni]);
                    mma_bf16(acc[mi][ni], ah[mi], bl[ni]);
                    mma_bf16(acc[mi][ni], al[mi], bh[ni]);
                }
        }

        if (has_next) {
            const uint32_t nb = (uint32_t)(buf ^ 1) * BUFB;
            cvt_store16(sm + nb + (size_t)am * ROWB + ak * 2,
                        sm + nb + ARR + (size_t)am * ROWB + ak * 2, fa);
            cvt_store16(sm + nb + 2 * ARR + (size_t)bn * ROWB + bk * 2,
                        sm + nb + 3 * ARR + (size_t)bn * ROWB + bk * 2, fb);
            __syncthreads();
        }
    }

    // ---- epilogue ----
#pragma unroll
    for (int mi = 0; mi < 4; mi++) {
#pragma unroll
        for (int ni = 0; ni < 4; ni++) {
            const int r0  = m0 + wy * 64 + mi * 16 + (lane >> 2);
            const int col = n0 + wx * 32 + ni * 8 + (lane & 3) * 2;
            const float2 bv = *reinterpret_cast<const float2*>(bias + col);
            float2 o0, o1;
            o0.x = acc[mi][ni][0] + bv.x;
            o0.y = acc[mi][ni][1] + bv.y;
            o1.x = acc[mi][ni][2] + bv.x;
            o1.y = acc[mi][ni][3] + bv.y;
            if (EPI == EPI_RES) {
                float2 ra = *reinterpret_cast<const float2*>(R + (size_t)r0 * N + col);
                float2 rb = *reinterpret_cast<const float2*>(R + (size_t)(r0 + 8) * N + col);
                o0.x += ra.x; o0.y += ra.y;
                o1.x += rb.x; o1.y += rb.y;
            } else if (EPI == EPI_GELU) {
                o0.x = gelu_f(o0.x); o0.y = gelu_f(o0.y);
                o1.x = gelu_f(o1.x); o1.y = gelu_f(o1.y);
            }
            *reinterpret_cast<float2*>(C + (size_t)r0 * N + col)       = o0;
            *reinterpret_cast<float2*>(C + (size_t)(r0 + 8) * N + col) = o1;
        }
    }
}

// ---------------------------------------------------------------------------
// Causal attention (SIMT fp32, online softmax)
// ---------------------------------------------------------------------------
__global__ __launch_bounds__(64)
void attn_kernel(const float* __restrict__ q,
                 const float* __restrict__ k,
                 const float* __restrict__ v,
                 const int* __restrict__ amask,
                 float* __restrict__ o)
{
    __shared__ float Ks[64][64];
    __shared__ float Vs[64][64];
    __shared__ int   msk[64];

    const int t  = threadIdx.x;
    const int bh = blockIdx.y;
    const int b  = bh >> 4;
    const int h  = bh & 15;
    const int qt = blockIdx.x;
    const int qi = qt * 64 + t;

    const size_t qoff = ((size_t)(b * Ss + qi)) * Dd + h * HDd;

    float4 q4[16];
#pragma unroll
    for (int i = 0; i < 16; i++)
        q4[i] = *reinterpret_cast<const float4*>(q + qoff + i * 4);

    float4 oa[16];
#pragma unroll
    for (int i = 0; i < 16; i++) oa[i] = make_float4(0.f, 0.f, 0.f, 0.f);

    float mrun = -1e30f, lrun = 0.f;
    const float scale = 0.125f;

    for (int kt = 0; kt <= qt; kt++) {
        __syncthreads();
#pragma unroll
        for (int i = 0; i < 16; i++) {
            const int f = i * 64 + t;
            const int r = f >> 4;
            const int c = (f & 15) << 2;
            const size_t src =
                ((size_t)(b * Ss + kt * 64 + r)) * Dd + h * HDd + c;
            *reinterpret_cast<float4*>(&Ks[r][c]) =
                *reinterpret_cast<const float4*>(k + src);
            *reinterpret_cast<float4*>(&Vs[r][c]) =
                *reinterpret_cast<const float4*>(v + src);
        }
        msk[t] = amask[b * Ss + kt * 64 + t];
        __syncthreads();

        const int kmax = (kt == qt) ? (t + 1) : 64;
        for (int kk = 0; kk < kmax; kk++) {
            if (!msk[kk]) continue;
            const float4* kr = reinterpret_cast<const float4*>(&Ks[kk][0]);
            float sA = 0.f, sB = 0.f, sC = 0.f, sD = 0.f;
#pragma unroll
            for (int i = 0; i < 16; i++) {
                float4 kv = kr[i];
                sA += q4[i].x * kv.x;
                sB += q4[i].y * kv.y;
                sC += q4[i].z * kv.z;
                sD += q4[i].w * kv.w;
            }
            const float sc = (sA + sB + sC + sD) * scale;
            const float mn = fmaxf(mrun, sc);
            const float alpha = __expf(mrun - mn);
            const float p     = __expf(sc - mn);
            lrun = lrun * alpha + p;
            mrun = mn;
            const float4* vr = reinterpret_cast<const float4*>(&Vs[kk][0]);
#pragma unroll
            for (int i = 0; i < 16; i++) {
                float4 vv = vr[i];
                oa[i].x = oa[i].x * alpha + p * vv.x;
                oa[i].y = oa[i].y * alpha + p * vv.y;
                oa[i].z = oa[i].z * alpha + p * vv.z;
                oa[i].w = oa[i].w * alpha + p * vv.w;
            }
        }
    }

    const float inv = (lrun > 0.f) ? (1.0f / lrun) : 0.f;
#pragma unroll
    for (int i = 0; i < 16; i++) {
        float4 ov = make_float4(oa[i].x * inv, oa[i].y * inv,
                                oa[i].z * inv, oa[i].w * inv);
        *reinterpret_cast<float4*>(o + qoff + i * 4) = ov;
    }
}

// ---------------------------------------------------------------------------
// Launch
// ---------------------------------------------------------------------------
extern "C" void kernel_launch(void* const* d_in, const int* in_sizes, int n_in,
                              void* d_out, int out_size)
{
    const int*   ids   = (const int*)d_in[0];
    const int*   amask = (const int*)d_in[1];
    const float* tok   = (const float*)d_in[2];
    const float* ln1g  = (const float*)d_in[3];
    const float* ln1b  = (const float*)d_in[4];
    const float* wq    = (const float*)d_in[5];
    const float* bq    = (const float*)d_in[6];
    const float* wk    = (const float*)d_in[7];
    const float* bk    = (const float*)d_in[8];
    const float* wv    = (const float*)d_in[9];
    const float* bv    = (const float*)d_in[10];
    const float* wo    = (const float*)d_in[11];
    const float* bo    = (const float*)d_in[12];
    const float* ln2g  = (const float*)d_in[13];
    const float* ln2b  = (const float*)d_in[14];
    const float* w1    = (const float*)d_in[15];
    const float* b1    = (const float*)d_in[16];
    const float* w2    = (const float*)d_in[17];
    const float* b2    = (const float*)d_in[18];
    const float* lnfg  = (const float*)d_in[19];
    const float* lnfb  = (const float*)d_in[20];
    float* out = (float*)d_out;

    float* scratch = nullptr;
    cudaGetSymbolAddress((void**)&scratch, g_scratch);

    float* X  = scratch + OFF_X;
    float* Hb = scratch + OFF_H;
    float* Qb = scratch + OFF_Q;
    float* Kb = scratch + OFF_K;
    float* Vb = scratch + OFF_V;
    float* Ab = scratch + OFF_A;
    float* Fb = scratch + OFF_F;

    cudaFuncSetAttribute(mma_gemm<EPI_NONE>,
                         cudaFuncAttributeMaxDynamicSharedMemorySize, GSMEM);
    cudaFuncSetAttribute(mma_gemm<EPI_RES>,
                         cudaFuncAttributeMaxDynamicSharedMemorySize, GSMEM);
    cudaFuncSetAttribute(mma_gemm<EPI_GELU>,
                         cudaFuncAttributeMaxDynamicSharedMemorySize, GSMEM);

    const dim3 gD(Dd / 128, Mrows / 128);    // (8, 32)
    const dim3 gF(Dff / 128, Mrows / 128);   // (32, 32)
    const dim3 gAttn(Ss / 64, Bb * Hh);

    embed_kernel<<<Mrows, 256>>>(ids, tok, X);

    for (int l = 0; l < Ll; l++) {
        const size_t wOff = (size_t)l * Dd * Dd;
        const size_t fOff = (size_t)l * Dd * Dff;

        ln_kernel<<<Mrows, 256>>>(X, ln1g + l * Dd, ln1b + l * Dd, Hb);

        mma_gemm<EPI_NONE><<<gD, 256, GSMEM>>>(Hb, wq + wOff, bq + l * Dd,
                                               nullptr, Qb, Dd, Dd);
        mma_gemm<EPI_NONE><<<gD, 256, GSMEM>>>(Hb, wk + wOff, bk + l * Dd,
                                               nullptr, Kb, Dd, Dd);
        mma_gemm<EPI_NONE><<<gD, 256, GSMEM>>>(Hb, wv + wOff, bv + l * Dd,
                                               nullptr, Vb, Dd, Dd);

        attn_kernel<<<gAttn, 64>>>(Qb, Kb, Vb, amask, Ab);

        mma_gemm<EPI_RES><<<gD, 256, GSMEM>>>(Ab, wo + wOff, bo + l * Dd,
                                              X, X, Dd, Dd);

        ln_kernel<<<Mrows, 256>>>(X, ln2g + l * Dd, ln2b + l * Dd, Hb);

        mma_gemm<EPI_GELU><<<gF, 256, GSMEM>>>(Hb, w1 + fOff, b1 + l * Dff,
                                               nullptr, Fb, Dff, Dd);
        mma_gemm<EPI_RES><<<gD, 256, GSMEM>>>(Fb, w2 + fOff, b2 + l * Dd,
                                              X, X, Dd, Dff);
    }

    ln_kernel<<<Mrows, 256>>>(X, lnfg, lnfb, out);
}